// round 1
// baseline (speedup 1.0000x reference)
#include <cuda_runtime.h>
#include <cstdint>

// Problem dims (fixed for this dataset)
#define MAX_N    8192
#define MAX_H2   256
#define MAX_H    128

// Scratch (static device globals — no allocation)
__device__ float g_h1[MAX_N * MAX_H2];     // relu(in_feat@W1+b1)  [N, 2H]
__device__ float g_allh[MAX_N * MAX_H];    // 5*relu(h1@W2+b2)     [N, H]

// ---------------------------------------------------------------------------
// Generic small MLP GEMM: C = max(A@W + bias, 0) * scale, optional copy to C2.
// BM=64, BN=64, BK=16, 256 threads, 4x4 micro-tile.
// ---------------------------------------------------------------------------
__global__ __launch_bounds__(256)
void mlp_kernel(const float* __restrict__ A, const float* __restrict__ W,
                const float* __restrict__ bias,
                float* __restrict__ C, float* __restrict__ C2,
                int M, int K, int Nout, float scale)
{
    __shared__ float As[16][68];   // [k][m], padded
    __shared__ float Bs[16][64];   // [k][n]

    const int tid = threadIdx.x;
    const int tx = tid & 15;        // 0..15  -> n
    const int ty = tid >> 4;        // 0..15  -> m
    const int bm = blockIdx.x * 64;
    const int bn = blockIdx.y * 64;

    // load mappings
    const int arow = tid >> 2;      // 0..63
    const int ak4  = tid & 3;       // 0..3  (float4 along K)
    const int bkr  = tid >> 4;      // 0..15
    const int bn4  = tid & 15;      // 0..15 (float4 along N)

    float acc[4][4];
#pragma unroll
    for (int m = 0; m < 4; m++)
#pragma unroll
        for (int n = 0; n < 4; n++) acc[m][n] = 0.f;

    for (int k0 = 0; k0 < K; k0 += 16) {
        float4 av = *reinterpret_cast<const float4*>(A + (size_t)(bm + arow) * K + k0 + ak4 * 4);
        As[ak4 * 4 + 0][arow] = av.x;
        As[ak4 * 4 + 1][arow] = av.y;
        As[ak4 * 4 + 2][arow] = av.z;
        As[ak4 * 4 + 3][arow] = av.w;
        float4 bv = *reinterpret_cast<const float4*>(W + (size_t)(k0 + bkr) * Nout + bn + bn4 * 4);
        *reinterpret_cast<float4*>(&Bs[bkr][bn4 * 4]) = bv;
        __syncthreads();

#pragma unroll
        for (int k = 0; k < 16; k++) {
            float a[4], b[4];
#pragma unroll
            for (int m = 0; m < 4; m++) a[m] = As[k][ty * 4 + m];
#pragma unroll
            for (int n = 0; n < 4; n++) b[n] = Bs[k][tx * 4 + n];
#pragma unroll
            for (int m = 0; m < 4; m++)
#pragma unroll
                for (int n = 0; n < 4; n++) acc[m][n] += a[m] * b[n];
        }
        __syncthreads();
    }

#pragma unroll
    for (int m = 0; m < 4; m++) {
        const int gr = bm + ty * 4 + m;
#pragma unroll
        for (int n = 0; n < 4; n++) {
            const int gc = bn + tx * 4 + n;
            float v = acc[m][n] + bias[gc];
            v = fmaxf(v, 0.f) * scale;
            C[(size_t)gr * Nout + gc] = v;
            if (C2) C2[(size_t)gr * Nout + gc] = v;
        }
    }
}

// ---------------------------------------------------------------------------
// recons = X @ X^T  (X = all_h, [N, 128]) exploiting symmetry.
// 128x128 output tile per block, K processed in 4 chunks of 32.
// Only upper-triangle blocks (bj >= bi) computed; mirror written for bj > bi.
// ---------------------------------------------------------------------------
__global__ __launch_bounds__(256)
void recons_kernel(const float* __restrict__ X, float* __restrict__ out,
                   int NB, int Nn, int Hd)
{
    __shared__ float As[32][132];   // [k][i] transposed tile of A-rows
    __shared__ float Bs[32][132];   // [k][j] transposed tile of B-rows

    // linear block index -> (bi, bj) with bi <= bj
    int rem = blockIdx.x;
    int bi = 0;
    while (rem >= NB - bi) { rem -= NB - bi; bi++; }
    const int bj = bi + rem;

    const int tid = threadIdx.x;
    const int lane = tid & 31;
    const int wid  = tid >> 5;
    const int tx = tid & 15;        // -> j micro-tile
    const int ty = tid >> 4;        // -> i micro-tile

    const float* Abase = X + (size_t)bi * 128 * Hd;
    const float* Bbase = X + (size_t)bj * 128 * Hd;

    float acc[8][8];
#pragma unroll
    for (int m = 0; m < 8; m++)
#pragma unroll
        for (int n = 0; n < 8; n++) acc[m][n] = 0.f;

    for (int kc = 0; kc < 4; kc++) {           // 4 K-chunks of 32
        // 64 warp-chunks total (32 per operand); each chunk = 16 rows x 8 k
        for (int ch = wid; ch < 64; ch += 8) {
            const int op = ch >> 5;
            const int c  = ch & 31;
            const int row = ((c & 7) << 4) + (lane >> 1);        // 0..127
            const int k4  = ((c >> 3) << 1) + (lane & 1);        // 0..7 (f4 within chunk)
            const float* src = op ? Bbase : Abase;
            float4 v = *reinterpret_cast<const float4*>(src + (size_t)row * Hd + kc * 32 + k4 * 4);
            float (*S)[132] = op ? Bs : As;
            S[k4 * 4 + 0][row] = v.x;
            S[k4 * 4 + 1][row] = v.y;
            S[k4 * 4 + 2][row] = v.z;
            S[k4 * 4 + 3][row] = v.w;
        }
        __syncthreads();

#pragma unroll
        for (int k = 0; k < 32; k++) {
            float4 a0 = *reinterpret_cast<const float4*>(&As[k][ty * 8]);
            float4 a1 = *reinterpret_cast<const float4*>(&As[k][ty * 8 + 4]);
            float4 b0 = *reinterpret_cast<const float4*>(&Bs[k][tx * 8]);
            float4 b1 = *reinterpret_cast<const float4*>(&Bs[k][tx * 8 + 4]);
            float a[8] = {a0.x, a0.y, a0.z, a0.w, a1.x, a1.y, a1.z, a1.w};
            float b[8] = {b0.x, b0.y, b0.z, b0.w, b1.x, b1.y, b1.z, b1.w};
#pragma unroll
            for (int m = 0; m < 8; m++)
#pragma unroll
                for (int n = 0; n < 8; n++) acc[m][n] += a[m] * b[n];
        }
        __syncthreads();
    }

    // direct tile write: rows bi*128.., cols bj*128..
#pragma unroll
    for (int m = 0; m < 8; m++) {
        const int gr = bi * 128 + ty * 8 + m;
        float* p = out + (size_t)gr * Nn + bj * 128 + tx * 8;
        *reinterpret_cast<float4*>(p)     = make_float4(acc[m][0], acc[m][1], acc[m][2], acc[m][3]);
        *reinterpret_cast<float4*>(p + 4) = make_float4(acc[m][4], acc[m][5], acc[m][6], acc[m][7]);
    }

    // mirror tile write (transpose): rows bj*128.., cols bi*128..
    if (bi != bj) {
#pragma unroll
        for (int n = 0; n < 8; n++) {
            const int gr = bj * 128 + tx * 8 + n;
            float* p = out + (size_t)gr * Nn + bi * 128 + ty * 8;
            *reinterpret_cast<float4*>(p)     = make_float4(acc[0][n], acc[1][n], acc[2][n], acc[3][n]);
            *reinterpret_cast<float4*>(p + 4) = make_float4(acc[4][n], acc[5][n], acc[6][n], acc[7][n]);
        }
    }
}

// ---------------------------------------------------------------------------
// Launch. Inputs (metadata order): in_feat, src, dst, W1, b1, W2, b2.
// _COEF = [5,0,0,0,0] exactly  =>  all_h = 5*relu(relu(x@W1+b1)@W2+b2),
// src/dst/deg are mathematically dead. Output = [recons (N,N), all_h (N,H)].
// ---------------------------------------------------------------------------
extern "C" void kernel_launch(void* const* d_in, const int* in_sizes, int n_in,
                              void* d_out, int out_size)
{
    const float* in_feat = (const float*)d_in[0];
    const float* W1      = (const float*)d_in[3];
    const float* b1      = (const float*)d_in[4];
    const float* W2      = (const float*)d_in[5];
    const float* b2      = (const float*)d_in[6];
    float* out = (float*)d_out;

    const int H2   = in_sizes[4];                  // 2H = 256
    const int INd  = in_sizes[3] / H2;             // 256
    const int N    = in_sizes[0] / INd;            // 8192
    const int H    = in_sizes[6];                  // 128

    float* h1p = nullptr;
    float* ahp = nullptr;
    cudaGetSymbolAddress((void**)&h1p, g_h1);
    cudaGetSymbolAddress((void**)&ahp, g_allh);

    // 1) h1 = relu(in_feat @ W1 + b1)
    {
        dim3 grid(N / 64, H2 / 64);
        mlp_kernel<<<grid, 256>>>(in_feat, W1, b1, h1p, nullptr, N, INd, H2, 1.0f);
    }
    // 2) all_h = 5 * relu(h1 @ W2 + b2)   (also written to output tail)
    {
        dim3 grid(N / 64, H / 64);
        float* tail = out + (size_t)N * N;
        mlp_kernel<<<grid, 256>>>(h1p, W2, b2, ahp, tail, N, H2, H, 5.0f);
    }
    // 3) recons = all_h @ all_h^T  (symmetric)
    {
        const int NB = N / 128;                    // 64
        const int nblocks = NB * (NB + 1) / 2;     // 2080
        recons_kernel<<<nblocks, 256>>>(ahp, out, NB, N, H);
    }
}

// round 4
// speedup vs baseline: 1.9770x; 1.9770x over previous
#include <cuda_runtime.h>
#include <cstdint>

#define MAX_N    8192
#define MAX_H2   256
#define MAX_H    128

__device__ float g_h1[MAX_N * MAX_H2];     // relu(in_feat@W1+b1)  [N, 2H]
__device__ float g_allh[MAX_N * MAX_H];    // 5*relu(h1@W2+b2)     [N, H]

__device__ __forceinline__ uint32_t f2tf32(float f) {
    uint32_t u;
    asm("cvt.rna.tf32.f32 %0, %1;" : "=r"(u) : "f"(f));
    return u;
}

__device__ __forceinline__ void mma_tf32(float& c0, float& c1, float& c2, float& c3,
                                         uint32_t a0, uint32_t a1, uint32_t a2, uint32_t a3,
                                         uint32_t b0, uint32_t b1) {
    asm volatile(
        "mma.sync.aligned.m16n8k8.row.col.f32.tf32.tf32.f32 "
        "{%0,%1,%2,%3}, {%4,%5,%6,%7}, {%8,%9}, {%0,%1,%2,%3};"
        : "+f"(c0), "+f"(c1), "+f"(c2), "+f"(c3)
        : "r"(a0), "r"(a1), "r"(a2), "r"(a3), "r"(b0), "r"(b1));
}

// ===========================================================================
// recons = X @ X^T  (X=[N,128] f32) via mma.sync tf32.
// One 128x128 tile pair (bi<=bj) per CTA. 256 thr = 2x4 warps, 64x32/warp.
// K in 2 smem chunks of 64. Mirror tile written via smem transpose staging.
// Dynamic smem: As[128][68] + Bs[128][68] f32 = 69632 B (2 CTA/SM).
// ===========================================================================
#define RCH   64            // K chunk
#define RPAD  68            // row stride (floats) in operand smem
#define TPAD  132           // row stride (floats) in transpose staging
#define R_SMEM_BYTES (2 * 128 * RPAD * 4)   // 69632

__global__ __launch_bounds__(256, 2)
void recons_mma(const float* __restrict__ X, float* __restrict__ out,
                int NB, int NN, int Hd)
{
    extern __shared__ float sm[];
    float* As = sm;
    float* BsReal = sm + 128 * RPAD;

    const int tid  = threadIdx.x;
    const int lane = tid & 31;
    const int wid  = tid >> 5;
    const int warp_m = wid >> 2;          // 0..1  (64-row half)
    const int warp_n = wid & 3;           // 0..3  (32-col quarter)
    const int grp  = lane >> 2;           // 0..7
    const int qd   = lane & 3;            // 0..3

    // upper-triangle pair decode (bi <= bj)
    int rem = blockIdx.x, bi = 0;
    while (rem >= NB - bi) { rem -= NB - bi; bi++; }
    const int bj = bi + rem;
    const bool diag = (bi == bj);
    float* Bs = diag ? As : BsReal;

    const float* Ap = X + (size_t)bi * 128 * Hd;
    const float* Bp = X + (size_t)bj * 128 * Hd;

    float acc[4][4][4];
#pragma unroll
    for (int mt = 0; mt < 4; mt++)
#pragma unroll
        for (int nt = 0; nt < 4; nt++)
#pragma unroll
            for (int q = 0; q < 4; q++) acc[mt][nt][q] = 0.f;

    for (int kc = 0; kc < 2; kc++) {
        // ---- load chunk: 128 rows x 64 floats -> tf32 bits in smem ----
#pragma unroll
        for (int it = 0; it < 8; it++) {
            const int i = tid + 256 * it;          // 0..2047
            const int row = i >> 4, k4 = i & 15;
            float4 v = *reinterpret_cast<const float4*>(Ap + (size_t)row * Hd + kc * RCH + k4 * 4);
            uint4 u = make_uint4(f2tf32(v.x), f2tf32(v.y), f2tf32(v.z), f2tf32(v.w));
            *reinterpret_cast<uint4*>(As + row * RPAD + k4 * 4) = u;
        }
        if (!diag) {
#pragma unroll
            for (int it = 0; it < 8; it++) {
                const int i = tid + 256 * it;
                const int row = i >> 4, k4 = i & 15;
                float4 v = *reinterpret_cast<const float4*>(Bp + (size_t)row * Hd + kc * RCH + k4 * 4);
                uint4 u = make_uint4(f2tf32(v.x), f2tf32(v.y), f2tf32(v.z), f2tf32(v.w));
                *reinterpret_cast<uint4*>(BsReal + row * RPAD + k4 * 4) = u;
            }
        }
        __syncthreads();

        // ---- compute: 8 k-steps of 8 ----
#pragma unroll
        for (int ks = 0; ks < 8; ks++) {
            const int k0 = ks * 8;
            uint32_t b[4][2];
#pragma unroll
            for (int nt = 0; nt < 4; nt++) {
                const int rowB = warp_n * 32 + nt * 8 + grp;
                const uint32_t* bp = reinterpret_cast<const uint32_t*>(Bs + rowB * RPAD + k0 + qd);
                b[nt][0] = bp[0];
                b[nt][1] = bp[4];
            }
#pragma unroll
            for (int mt = 0; mt < 4; mt++) {
                const int rowA = warp_m * 64 + mt * 16 + grp;
                const uint32_t* ap0 = reinterpret_cast<const uint32_t*>(As + rowA * RPAD + k0 + qd);
                const uint32_t* ap1 = reinterpret_cast<const uint32_t*>(As + (rowA + 8) * RPAD + k0 + qd);
                uint32_t a0 = ap0[0], a1 = ap1[0], a2 = ap0[4], a3 = ap1[4];
#pragma unroll
                for (int nt = 0; nt < 4; nt++)
                    mma_tf32(acc[mt][nt][0], acc[mt][nt][1], acc[mt][nt][2], acc[mt][nt][3],
                             a0, a1, a2, a3, b[nt][0], b[nt][1]);
            }
        }
        __syncthreads();
    }

    // ---- direct tile store (rows bi*, cols bj*) ----
#pragma unroll
    for (int mt = 0; mt < 4; mt++) {
        const int r0 = bi * 128 + warp_m * 64 + mt * 16 + grp;
#pragma unroll
        for (int nt = 0; nt < 4; nt++) {
            const int c0 = bj * 128 + warp_n * 32 + nt * 8 + 2 * qd;
            *reinterpret_cast<float2*>(out + (size_t)r0 * NN + c0) =
                make_float2(acc[mt][nt][0], acc[mt][nt][1]);
            *reinterpret_cast<float2*>(out + (size_t)(r0 + 8) * NN + c0) =
                make_float2(acc[mt][nt][2], acc[mt][nt][3]);
        }
    }

    // ---- mirror tile via smem transpose staging ----
    if (!diag) {
        float* sT = sm;                        // reuse operand smem (67.6KB <= 68KB)
#pragma unroll
        for (int mt = 0; mt < 4; mt++) {
            const int r = warp_m * 64 + mt * 16 + grp;     // local row
#pragma unroll
            for (int nt = 0; nt < 4; nt++) {
                const int c = warp_n * 32 + nt * 8 + 2 * qd;  // local col
                sT[c * TPAD + r]           = acc[mt][nt][0];
                sT[(c + 1) * TPAD + r]     = acc[mt][nt][1];
                sT[c * TPAD + r + 8]       = acc[mt][nt][2];
                sT[(c + 1) * TPAD + r + 8] = acc[mt][nt][3];
            }
        }
        __syncthreads();
#pragma unroll
        for (int it = 0; it < 16; it++) {
            const int i = tid + 256 * it;          // 0..4095
            const int rc = i >> 5, q = i & 31;     // mirror row rc (= orig col)
            float4 v = *reinterpret_cast<const float4*>(sT + rc * TPAD + q * 4);
            *reinterpret_cast<float4*>(out + (size_t)(bj * 128 + rc) * NN + bi * 128 + q * 4) = v;
        }
    }
}

// ===========================================================================
// MLP GEMM #1: 128x128 tile, 256 threads, 8x8 split micro-tile. fp32.
// ===========================================================================
__global__ __launch_bounds__(256)
void mlp128_kernel(const float* __restrict__ A, const float* __restrict__ W,
                   const float* __restrict__ bias,
                   float* __restrict__ C, float* __restrict__ C2,
                   int K, int Nout, float scale)
{
    __shared__ float As[16][132];
    __shared__ float Bs[16][128];

    const int tid = threadIdx.x;
    const int tx = tid & 15;
    const int ty = tid >> 4;
    const int bm = blockIdx.x * 128;
    const int bn = blockIdx.y * 128;

    float acc[8][8];
#pragma unroll
    for (int m = 0; m < 8; m++)
#pragma unroll
        for (int n = 0; n < 8; n++) acc[m][n] = 0.f;

    for (int k0 = 0; k0 < K; k0 += 16) {
#pragma unroll
        for (int i = 0; i < 2; i++) {
            const int idx = tid + 256 * i;
            const int row = idx >> 2, ak = idx & 3;
            float4 v = *reinterpret_cast<const float4*>(A + (size_t)(bm + row) * K + k0 + ak * 4);
            As[ak * 4 + 0][row] = v.x;
            As[ak * 4 + 1][row] = v.y;
            As[ak * 4 + 2][row] = v.z;
            As[ak * 4 + 3][row] = v.w;
        }
#pragma unroll
        for (int i = 0; i < 2; i++) {
            const int idx = tid + 256 * i;
            const int kr = idx >> 5, nf = idx & 31;
            float4 v = *reinterpret_cast<const float4*>(W + (size_t)(k0 + kr) * Nout + bn + nf * 4);
            *reinterpret_cast<float4*>(&Bs[kr][nf * 4]) = v;
        }
        __syncthreads();

#pragma unroll
        for (int k = 0; k < 16; k++) {
            float4 a0 = *reinterpret_cast<const float4*>(&As[k][ty * 4]);
            float4 a1 = *reinterpret_cast<const float4*>(&As[k][64 + ty * 4]);
            float4 b0 = *reinterpret_cast<const float4*>(&Bs[k][tx * 4]);
            float4 b1 = *reinterpret_cast<const float4*>(&Bs[k][64 + tx * 4]);
            float a[8] = {a0.x, a0.y, a0.z, a0.w, a1.x, a1.y, a1.z, a1.w};
            float b[8] = {b0.x, b0.y, b0.z, b0.w, b1.x, b1.y, b1.z, b1.w};
#pragma unroll
            for (int m = 0; m < 8; m++)
#pragma unroll
                for (int n = 0; n < 8; n++) acc[m][n] += a[m] * b[n];
        }
        __syncthreads();
    }

#pragma unroll
    for (int mh = 0; mh < 2; mh++)
#pragma unroll
    for (int m = 0; m < 4; m++) {
        const int gr = bm + mh * 64 + ty * 4 + m;
#pragma unroll
        for (int nh = 0; nh < 2; nh++) {
            const int gc = bn + nh * 64 + tx * 4;
            float4 bv = *reinterpret_cast<const float4*>(bias + gc);
            float4 o;
            o.x = fmaxf(acc[mh * 4 + m][nh * 4 + 0] + bv.x, 0.f) * scale;
            o.y = fmaxf(acc[mh * 4 + m][nh * 4 + 1] + bv.y, 0.f) * scale;
            o.z = fmaxf(acc[mh * 4 + m][nh * 4 + 2] + bv.z, 0.f) * scale;
            o.w = fmaxf(acc[mh * 4 + m][nh * 4 + 3] + bv.w, 0.f) * scale;
            *reinterpret_cast<float4*>(C + (size_t)gr * Nout + gc) = o;
            if (C2) *reinterpret_cast<float4*>(C2 + (size_t)gr * Nout + gc) = o;
        }
    }
}

// ===========================================================================
// MLP GEMM #2 (validated 64x64 kernel; good spread for Nout=128)
// ===========================================================================
__global__ __launch_bounds__(256)
void mlp_kernel(const float* __restrict__ A, const float* __restrict__ W,
                const float* __restrict__ bias,
                float* __restrict__ C, float* __restrict__ C2,
                int M, int K, int Nout, float scale)
{
    __shared__ float As[16][68];
    __shared__ float Bs[16][64];

    const int tid = threadIdx.x;
    const int tx = tid & 15;
    const int ty = tid >> 4;
    const int bm = blockIdx.x * 64;
    const int bn = blockIdx.y * 64;

    const int arow = tid >> 2;
    const int ak4  = tid & 3;
    const int bkr  = tid >> 4;
    const int bn4  = tid & 15;

    float acc[4][4];
#pragma unroll
    for (int m = 0; m < 4; m++)
#pragma unroll
        for (int n = 0; n < 4; n++) acc[m][n] = 0.f;

    for (int k0 = 0; k0 < K; k0 += 16) {
        float4 av = *reinterpret_cast<const float4*>(A + (size_t)(bm + arow) * K + k0 + ak4 * 4);
        As[ak4 * 4 + 0][arow] = av.x;
        As[ak4 * 4 + 1][arow] = av.y;
        As[ak4 * 4 + 2][arow] = av.z;
        As[ak4 * 4 + 3][arow] = av.w;
        float4 bv = *reinterpret_cast<const float4*>(W + (size_t)(k0 + bkr) * Nout + bn + bn4 * 4);
        *reinterpret_cast<float4*>(&Bs[bkr][bn4 * 4]) = bv;
        __syncthreads();

#pragma unroll
        for (int k = 0; k < 16; k++) {
            float a[4], b[4];
#pragma unroll
            for (int m = 0; m < 4; m++) a[m] = As[k][ty * 4 + m];
#pragma unroll
            for (int n = 0; n < 4; n++) b[n] = Bs[k][tx * 4 + n];
#pragma unroll
            for (int m = 0; m < 4; m++)
#pragma unroll
                for (int n = 0; n < 4; n++) acc[m][n] += a[m] * b[n];
        }
        __syncthreads();
    }

#pragma unroll
    for (int m = 0; m < 4; m++) {
        const int gr = bm + ty * 4 + m;
#pragma unroll
        for (int n = 0; n < 4; n++) {
            const int gc = bn + tx * 4 + n;
            float v = acc[m][n] + bias[gc];
            v = fmaxf(v, 0.f) * scale;
            C[(size_t)gr * Nout + gc] = v;
            if (C2) C2[(size_t)gr * Nout + gc] = v;
        }
    }
}

// ===========================================================================
// Launch. _COEF = [5,0,0,0,0] exactly => all_h = 5*relu(relu(x@W1+b1)@W2+b2);
// src/dst/deg dead. Output = [recons (N,N), all_h (N,H)].
// ===========================================================================
extern "C" void kernel_launch(void* const* d_in, const int* in_sizes, int n_in,
                              void* d_out, int out_size)
{
    const float* in_feat = (const float*)d_in[0];
    const float* W1      = (const float*)d_in[3];
    const float* b1      = (const float*)d_in[4];
    const float* W2      = (const float*)d_in[5];
    const float* b2      = (const float*)d_in[6];
    float* out = (float*)d_out;

    const int H2   = in_sizes[4];                  // 256
    const int INd  = in_sizes[3] / H2;             // 256
    const int N    = in_sizes[0] / INd;            // 8192
    const int H    = in_sizes[6];                  // 128

    float* h1p = nullptr;
    float* ahp = nullptr;
    cudaGetSymbolAddress((void**)&h1p, g_h1);
    cudaGetSymbolAddress((void**)&ahp, g_allh);

    cudaFuncSetAttribute(recons_mma, cudaFuncAttributeMaxDynamicSharedMemorySize, R_SMEM_BYTES);

    // 1) h1 = relu(in_feat @ W1 + b1)
    {
        dim3 grid(N / 128, H2 / 128);
        mlp128_kernel<<<grid, 256>>>(in_feat, W1, b1, h1p, nullptr, INd, H2, 1.0f);
    }
    // 2) all_h = 5 * relu(h1 @ W2 + b2)  (also to output tail)
    {
        dim3 grid(N / 64, H / 64);
        float* tail = out + (size_t)N * N;
        mlp_kernel<<<grid, 256>>>(h1p, W2, b2, ahp, tail, N, H2, H, 5.0f);
    }
    // 3) recons = all_h @ all_h^T via mma.sync tf32, symmetric tile pairs
    {
        const int NB = N / 128;                    // 64
        const int nblocks = NB * (NB + 1) / 2;     // 2080
        recons_mma<<<nblocks, 256, R_SMEM_BYTES>>>(ahp, out, NB, N, H);
    }
}

// round 6
// speedup vs baseline: 2.1413x; 1.0831x over previous
#include <cuda_runtime.h>
#include <cstdint>

#define MAX_N    8192
#define MAX_H2   256
#define MAX_H    128

__device__ float    g_h1[MAX_N * MAX_H2];       // relu(in_feat@W1+b1)  [N, 2H]
__device__ uint32_t g_allh_tf[MAX_N * MAX_H];   // tf32 bits of all_h   [N, H]
__device__ float    g_W1T[MAX_H2 * MAX_H2];     // W1^T [256n][256k]
__device__ float    g_W2T[MAX_H  * MAX_H2];     // W2^T [128n][256k]

__device__ __forceinline__ uint32_t f2tf32(float f) {
    uint32_t u;
    asm("cvt.rna.tf32.f32 %0, %1;" : "=r"(u) : "f"(f));
    return u;
}
__device__ __forceinline__ void mma_tf32(float& c0, float& c1, float& c2, float& c3,
                                         uint32_t a0, uint32_t a1, uint32_t a2, uint32_t a3,
                                         uint32_t b0, uint32_t b1) {
    asm volatile(
        "mma.sync.aligned.m16n8k8.row.col.f32.tf32.tf32.f32 "
        "{%0,%1,%2,%3}, {%4,%5,%6,%7}, {%8,%9}, {%0,%1,%2,%3};"
        : "+f"(c0), "+f"(c1), "+f"(c2), "+f"(c3)
        : "r"(a0), "r"(a1), "r"(a2), "r"(a3), "r"(b0), "r"(b1));
}
__device__ __forceinline__ uint32_t smem_a32(const void* p) {
    return (uint32_t)__cvta_generic_to_shared(p);
}
__device__ __forceinline__ void cp16(uint32_t dst, const void* src) {
    asm volatile("cp.async.cg.shared.global [%0], [%1], 16;" :: "r"(dst), "l"(src) : "memory");
}
#define CP_COMMIT() asm volatile("cp.async.commit_group;" ::: "memory")
#define CP_WAIT1()  asm volatile("cp.async.wait_group 1;" ::: "memory")
#define CP_WAIT0()  asm volatile("cp.async.wait_group 0;" ::: "memory")

// ===========================================================================
// recons = X @ X^T, X pre-converted to tf32 bits [N,128].
// 128x128 tile pair (bi<=bj) per CTA. 8 warps (2x4), warp tile 64x32.
// K=128 in 4 chunks of 32, cp.async double-buffered (2-deep).
// smem: A bufs [2][128][36] u32 + B bufs [2][128][36] u32 = 73728 B.
// Mirror tile written via smem transpose staging (reuses buffers).
// ===========================================================================
#define RPAD  36
#define TPAD  132
#define R_SMEM_BYTES (4 * 128 * RPAD * 4)     // 73728

__global__ __launch_bounds__(256, 2)
void recons_mma(const uint32_t* __restrict__ Xt, float* __restrict__ out, int NB, int NN)
{
    extern __shared__ uint32_t sm_u[];
    const int tid  = threadIdx.x;
    const int lane = tid & 31;
    const int wid  = tid >> 5;
    const int warp_m = wid >> 2;
    const int warp_n = wid & 3;
    const int grp  = lane >> 2;
    const int qd   = lane & 3;

    int rem = blockIdx.x, bi = 0;
    while (rem >= NB - bi) { rem -= NB - bi; bi++; }
    const int bj = bi + rem;
    const bool diag = (bi == bj);

    const uint32_t* Ap = Xt + (size_t)bi * 128 * 128;
    const uint32_t* Bp = Xt + (size_t)bj * 128 * 128;

    uint32_t* Abuf[2] = { sm_u,                sm_u + 128 * RPAD };
    uint32_t* Bbuf[2] = { sm_u + 2*128*RPAD,   sm_u + 3*128*RPAD };

    auto load_chunk = [&](int kc, int b) {
#pragma unroll
        for (int it = 0; it < 4; it++) {
            const int i = tid + 256 * it;          // 0..1023
            const int row = i >> 3, seg = i & 7;
            cp16(smem_a32(Abuf[b] + row * RPAD + seg * 4),
                 Ap + (size_t)row * 128 + kc * 32 + seg * 4);
        }
        if (!diag) {
#pragma unroll
            for (int it = 0; it < 4; it++) {
                const int i = tid + 256 * it;
                const int row = i >> 3, seg = i & 7;
                cp16(smem_a32(Bbuf[b] + row * RPAD + seg * 4),
                     Bp + (size_t)row * 128 + kc * 32 + seg * 4);
            }
        }
        CP_COMMIT();
    };

    float acc[4][4][4];
#pragma unroll
    for (int mt = 0; mt < 4; mt++)
#pragma unroll
        for (int nt = 0; nt < 4; nt++)
#pragma unroll
            for (int q = 0; q < 4; q++) acc[mt][nt][q] = 0.f;

    load_chunk(0, 0);
    load_chunk(1, 1);

    for (int kc = 0; kc < 4; kc++) {
        const int b = kc & 1;
        if (kc < 3) CP_WAIT1(); else CP_WAIT0();
        __syncthreads();

        const uint32_t* As = Abuf[b];
        const uint32_t* Bs = diag ? Abuf[b] : Bbuf[b];
#pragma unroll
        for (int ks = 0; ks < 4; ks++) {
            const int k0 = ks * 8;
            uint32_t bfr[4][2];
#pragma unroll
            for (int nt = 0; nt < 4; nt++) {
                const uint32_t* bp = Bs + (warp_n * 32 + nt * 8 + grp) * RPAD + k0 + qd;
                bfr[nt][0] = bp[0];
                bfr[nt][1] = bp[4];
            }
#pragma unroll
            for (int mt = 0; mt < 4; mt++) {
                const int rowA = warp_m * 64 + mt * 16 + grp;
                const uint32_t* ap0 = As + rowA * RPAD + k0 + qd;
                const uint32_t* ap1 = As + (rowA + 8) * RPAD + k0 + qd;
                uint32_t a0 = ap0[0], a1 = ap1[0], a2 = ap0[4], a3 = ap1[4];
#pragma unroll
                for (int nt = 0; nt < 4; nt++)
                    mma_tf32(acc[mt][nt][0], acc[mt][nt][1], acc[mt][nt][2], acc[mt][nt][3],
                             a0, a1, a2, a3, bfr[nt][0], bfr[nt][1]);
            }
        }
        __syncthreads();
        if (kc < 2) load_chunk(kc + 2, b);
    }

    // ---- direct tile store ----
#pragma unroll
    for (int mt = 0; mt < 4; mt++) {
        const int r0 = bi * 128 + warp_m * 64 + mt * 16 + grp;
#pragma unroll
        for (int nt = 0; nt < 4; nt++) {
            const int c0 = bj * 128 + warp_n * 32 + nt * 8 + 2 * qd;
            *reinterpret_cast<float2*>(out + (size_t)r0 * NN + c0) =
                make_float2(acc[mt][nt][0], acc[mt][nt][1]);
            *reinterpret_cast<float2*>(out + (size_t)(r0 + 8) * NN + c0) =
                make_float2(acc[mt][nt][2], acc[mt][nt][3]);
        }
    }

    // ---- mirror tile via smem transpose staging ----
    if (!diag) {
        float* sT = reinterpret_cast<float*>(sm_u);     // 128*132*4 = 67584 <= 73728
#pragma unroll
        for (int mt = 0; mt < 4; mt++) {
            const int r = warp_m * 64 + mt * 16 + grp;
#pragma unroll
            for (int nt = 0; nt < 4; nt++) {
                const int c = warp_n * 32 + nt * 8 + 2 * qd;
                sT[c * TPAD + r]           = acc[mt][nt][0];
                sT[(c + 1) * TPAD + r]     = acc[mt][nt][1];
                sT[c * TPAD + r + 8]       = acc[mt][nt][2];
                sT[(c + 1) * TPAD + r + 8] = acc[mt][nt][3];
            }
        }
        __syncthreads();
#pragma unroll
        for (int it = 0; it < 16; it++) {
            const int i = tid + 256 * it;
            const int rc = i >> 5, q = i & 31;
            float4 v = *reinterpret_cast<const float4*>(sT + rc * TPAD + q * 4);
            *reinterpret_cast<float4*>(out + (size_t)(bj * 128 + rc) * NN + bi * 128 + q * 4) = v;
        }
    }
}

// ===========================================================================
// 3xTF32 MLP GEMM: C = relu(A @ W + bias) * scale, W given TRANSPOSED
// (WT[n][k]). Tile BM x 128, K-chunks of 32. Error-compensated split:
// x = hi + lo; acc += hi*hi + hi*lo + lo*hi  (fp32-class accuracy).
// Outputs (each optional): C f32 [*, Nout], C2 f32 copy, Ctf tf32 bits.
// ===========================================================================
template<int BM>
__global__ __launch_bounds__(256)
void gemm3t(const float* __restrict__ A, const float* __restrict__ WT,
            const float* __restrict__ bias,
            float* __restrict__ C, float* __restrict__ C2, uint32_t* __restrict__ Ctf,
            int K, int Nout, float scale)
{
    constexpr int MT = BM / 32;                 // m16 tiles per warp
    extern __shared__ uint32_t sm_u[];
    uint32_t* Ahi = sm_u;
    uint32_t* Alo = sm_u + BM * RPAD;
    uint32_t* Bhi = sm_u + 2 * BM * RPAD;
    uint32_t* Blo = sm_u + 2 * BM * RPAD + 128 * RPAD;

    const int tid  = threadIdx.x;
    const int lane = tid & 31;
    const int wid  = tid >> 5;
    const int warp_m = wid >> 2;
    const int warp_n = wid & 3;
    const int grp  = lane >> 2;
    const int qd   = lane & 3;
    const int bm = blockIdx.x * BM;
    const int bn = blockIdx.y * 128;

    float acc[MT][4][4];
#pragma unroll
    for (int mt = 0; mt < MT; mt++)
#pragma unroll
        for (int nt = 0; nt < 4; nt++)
#pragma unroll
            for (int q = 0; q < 4; q++) acc[mt][nt][q] = 0.f;

    for (int kc = 0; kc < K; kc += 32) {
#pragma unroll
        for (int it = 0; it < BM * 8 / 256; it++) {
            const int i = tid + 256 * it;
            const int row = i >> 3, seg = i & 7;
            float4 v = *reinterpret_cast<const float4*>(A + (size_t)(bm + row) * K + kc + seg * 4);
            uint4 hi = make_uint4(f2tf32(v.x), f2tf32(v.y), f2tf32(v.z), f2tf32(v.w));
            uint4 lo = make_uint4(f2tf32(v.x - __uint_as_float(hi.x)),
                                  f2tf32(v.y - __uint_as_float(hi.y)),
                                  f2tf32(v.z - __uint_as_float(hi.z)),
                                  f2tf32(v.w - __uint_as_float(hi.w)));
            *reinterpret_cast<uint4*>(Ahi + row * RPAD + seg * 4) = hi;
            *reinterpret_cast<uint4*>(Alo + row * RPAD + seg * 4) = lo;
        }
#pragma unroll
        for (int it = 0; it < 4; it++) {
            const int i = tid + 256 * it;
            const int row = i >> 3, seg = i & 7;
            float4 v = *reinterpret_cast<const float4*>(WT + (size_t)(bn + row) * K + kc + seg * 4);
            uint4 hi = make_uint4(f2tf32(v.x), f2tf32(v.y), f2tf32(v.z), f2tf32(v.w));
            uint4 lo = make_uint4(f2tf32(v.x - __uint_as_float(hi.x)),
                                  f2tf32(v.y - __uint_as_float(hi.y)),
                                  f2tf32(v.z - __uint_as_float(hi.z)),
                                  f2tf32(v.w - __uint_as_float(hi.w)));
            *reinterpret_cast<uint4*>(Bhi + row * RPAD + seg * 4) = hi;
            *reinterpret_cast<uint4*>(Blo + row * RPAD + seg * 4) = lo;
        }
        __syncthreads();

#pragma unroll
        for (int ks = 0; ks < 4; ks++) {
            const int k0 = ks * 8;
            uint32_t bh[4][2], bl[4][2];
#pragma unroll
            for (int nt = 0; nt < 4; nt++) {
                const int ro = (warp_n * 32 + nt * 8 + grp) * RPAD + k0 + qd;
                bh[nt][0] = Bhi[ro];  bh[nt][1] = Bhi[ro + 4];
                bl[nt][0] = Blo[ro];  bl[nt][1] = Blo[ro + 4];
            }
#pragma unroll
            for (int mt = 0; mt < MT; mt++) {
                const int rowA = warp_m * (BM / 2) + mt * 16 + grp;
                const int o0 = rowA * RPAD + k0 + qd;
                const int o1 = (rowA + 8) * RPAD + k0 + qd;
                uint32_t ah0 = Ahi[o0], ah1 = Ahi[o1], ah2 = Ahi[o0 + 4], ah3 = Ahi[o1 + 4];
                uint32_t al0 = Alo[o0], al1 = Alo[o1], al2 = Alo[o0 + 4], al3 = Alo[o1 + 4];
#pragma unroll
                for (int nt = 0; nt < 4; nt++) {
                    mma_tf32(acc[mt][nt][0], acc[mt][nt][1], acc[mt][nt][2], acc[mt][nt][3],
                             ah0, ah1, ah2, ah3, bh[nt][0], bh[nt][1]);
                    mma_tf32(acc[mt][nt][0], acc[mt][nt][1], acc[mt][nt][2], acc[mt][nt][3],
                             ah0, ah1, ah2, ah3, bl[nt][0], bl[nt][1]);
                    mma_tf32(acc[mt][nt][0], acc[mt][nt][1], acc[mt][nt][2], acc[mt][nt][3],
                             al0, al1, al2, al3, bh[nt][0], bh[nt][1]);
                }
            }
        }
        __syncthreads();
    }

    // epilogue
#pragma unroll
    for (int mt = 0; mt < MT; mt++) {
        const int r0 = bm + warp_m * (BM / 2) + mt * 16 + grp;
#pragma unroll
        for (int nt = 0; nt < 4; nt++) {
            const int c0 = bn + warp_n * 32 + nt * 8 + 2 * qd;
            const float bz0 = bias[c0], bz1 = bias[c0 + 1];
            float v00 = fmaxf(acc[mt][nt][0] + bz0, 0.f) * scale;
            float v01 = fmaxf(acc[mt][nt][1] + bz1, 0.f) * scale;
            float v10 = fmaxf(acc[mt][nt][2] + bz0, 0.f) * scale;
            float v11 = fmaxf(acc[mt][nt][3] + bz1, 0.f) * scale;
            if (C) {
                *reinterpret_cast<float2*>(C + (size_t)r0 * Nout + c0)       = make_float2(v00, v01);
                *reinterpret_cast<float2*>(C + (size_t)(r0 + 8) * Nout + c0) = make_float2(v10, v11);
            }
            if (C2) {
                *reinterpret_cast<float2*>(C2 + (size_t)r0 * Nout + c0)       = make_float2(v00, v01);
                *reinterpret_cast<float2*>(C2 + (size_t)(r0 + 8) * Nout + c0) = make_float2(v10, v11);
            }
            if (Ctf) {
                *reinterpret_cast<uint2*>(Ctf + (size_t)r0 * Nout + c0) =
                    make_uint2(f2tf32(v00), f2tf32(v01));
                *reinterpret_cast<uint2*>(Ctf + (size_t)(r0 + 8) * Nout + c0) =
                    make_uint2(f2tf32(v10), f2tf32(v11));
            }
        }
    }
}

// ===========================================================================
// Tiled transpose: dst[c][r] = src[r][c], src [R][Cc].
// ===========================================================================
__global__ void transpose_k(const float* __restrict__ src, float* __restrict__ dst,
                            int R, int Cc)
{
    __shared__ float t[32][33];
    const int cb = blockIdx.x * 32, rb = blockIdx.y * 32;
    const int x = threadIdx.x, y = threadIdx.y;
#pragma unroll
    for (int i = 0; i < 32; i += 8) {
        const int r = rb + y + i, c = cb + x;
        if (r < R && c < Cc) t[y + i][x] = src[(size_t)r * Cc + c];
    }
    __syncthreads();
#pragma unroll
    for (int i = 0; i < 32; i += 8) {
        const int c = cb + y + i, r = rb + x;
        if (c < Cc && r < R) dst[(size_t)c * R + r] = t[x][y + i];
    }
}

// ===========================================================================
// Launch. _COEF = [5,0,0,0,0] exactly => all_h = 5*relu(relu(x@W1+b1)@W2+b2);
// src/dst/deg dead. Output = [recons (N,N), all_h (N,H)].
// ===========================================================================
extern "C" void kernel_launch(void* const* d_in, const int* in_sizes, int n_in,
                              void* d_out, int out_size)
{
    const float* in_feat = (const float*)d_in[0];
    const float* W1      = (const float*)d_in[3];
    const float* b1      = (const float*)d_in[4];
    const float* W2      = (const float*)d_in[5];
    const float* b2      = (const float*)d_in[6];
    float* out = (float*)d_out;

    const int H2   = in_sizes[4];                  // 256
    const int INd  = in_sizes[3] / H2;             // 256
    const int N    = in_sizes[0] / INd;            // 8192
    const int H    = in_sizes[6];                  // 128

    float *h1p, *w1t, *w2t;
    uint32_t* ahtf;
    cudaGetSymbolAddress((void**)&h1p, g_h1);
    cudaGetSymbolAddress((void**)&w1t, g_W1T);
    cudaGetSymbolAddress((void**)&w2t, g_W2T);
    cudaGetSymbolAddress((void**)&ahtf, g_allh_tf);

    const int SM128 = (2 * 128 + 2 * 128) * RPAD * 4;   // 73728
    const int SM64  = (2 * 64 + 2 * 128) * RPAD * 4;    // 55296
    cudaFuncSetAttribute(gemm3t<128>, cudaFuncAttributeMaxDynamicSharedMemorySize, SM128);
    cudaFuncSetAttribute(gemm3t<64>,  cudaFuncAttributeMaxDynamicSharedMemorySize, SM64);
    cudaFuncSetAttribute(recons_mma,  cudaFuncAttributeMaxDynamicSharedMemorySize, R_SMEM_BYTES);

    // 0) transpose weights (tiny)
    {
        dim3 blk(32, 8);
        transpose_k<<<dim3(H2 / 32, H2 / 32), blk>>>(W1, w1t, H2, H2);   // W1[256k][256n]
        transpose_k<<<dim3(H / 32, H2 / 32), blk>>>(W2, w2t, H2, H);     // W2[256k][128n]
    }
    // 1) h1 = relu(in_feat @ W1 + b1)   (3xTF32)
    gemm3t<128><<<dim3(N / 128, H2 / 128), 256, SM128>>>(
        in_feat, w1t, b1, h1p, nullptr, nullptr, INd, H2, 1.0f);
    // 2) all_h = 5*relu(h1 @ W2 + b2) -> out tail (f32) + tf32 bits for recons
    gemm3t<64><<<dim3(N / 64, H / 128), 256, SM64>>>(
        h1p, w2t, b2, nullptr, out + (size_t)N * N, ahtf, H2, H, 5.0f);
    // 3) recons = all_h @ all_h^T (tf32 mma, symmetric pairs, cp.async pipeline)
    {
        const int NB = N / 128;                    // 64
        const int nblocks = NB * (NB + 1) / 2;     // 2080
        recons_mma<<<nblocks, 256, R_SMEM_BYTES>>>(ahtf, out, NB, N);
    }
}